// round 12
// baseline (speedup 1.0000x reference)
#include <cuda_runtime.h>
#include <cuda_fp16.h>
#include <math.h>

#define NUM_USERS 60000
#define NUM_ITEMS 40000
#define NUM_NODES 100000
#define EMB 64
#define HID 32
#define N_EDGES 1600000
#define BATCH 16384

#define SCAN_BLK 1024
#define NB ((NUM_NODES + SCAN_BLK - 1) / SCAN_BLK)   // 98

#define ST_AGG  (1 << 30)
#define ST_INCL (2 << 30)
#define ST_VAL  0x3FFFFFFF

// ---------------- device scratch (allocation-free rule) ----------------
__device__ __align__(16) __half g_h1h[NUM_NODES * HID];   // lin1 out, fp16 (64B/row)
__device__ __align__(16) __half g_yh[NUM_NODES * HID];    // relu(agg1), fp16 (64B/row)
__device__ __align__(16) float  g_aggT[HID * NUM_NODES];  // layer-2 agg, TRANSPOSED [k][node]
__device__ float g_s[NUM_NODES];                          // per-row sum of vals
__device__ int   g_counts[NUM_NODES];                     // degree hist / cursor (zeroed by predict tail)
__device__ int   g_row_ptr[NUM_NODES + 1];
__device__ int   g_tile_state[NB];                        // lookback states (zeroed by predict tail)
__device__ __align__(8) int2 g_epk[N_EDGES];              // (col, val-bits), CSR order

// ---------------------------------------------------------------------------
// Fused lin1 + degree histogram (warp-role split). Counts pre-zeroed invariant.
__global__ void lin1_hist_kernel(const float* __restrict__ uemb,
                                 const float* __restrict__ iemb,
                                 const float* __restrict__ W,
                                 const float* __restrict__ b,
                                 const int* __restrict__ rows) {
    int lane = threadIdx.x & 31;
    int wid  = blockIdx.x * (blockDim.x >> 5) + (threadIdx.x >> 5);
    int nwarps = gridDim.x * (blockDim.x >> 5);
    int hist_warps = nwarps >> 2;

    if (wid < hist_warps) {
        int t = wid * 32 + lane;
        int nthr = hist_warps * 32;
        for (int e4 = t * 4; e4 < N_EDGES; e4 += nthr * 4) {
            int4 r4 = *(const int4*)(rows + e4);      // N_EDGES % 4 == 0
            atomicAdd(&g_counts[r4.x], 1);
            atomicAdd(&g_counts[r4.y], 1);
            atomicAdd(&g_counts[r4.z], 1);
            atomicAdd(&g_counts[r4.w], 1);
        }
        return;
    }

    float w[EMB];
#pragma unroll
    for (int k = 0; k < EMB; k++) w[k] = __ldg(&W[lane * EMB + k]);
    float bias = __ldg(&b[lane]);

    int wl = wid - hist_warps;
    int nl = nwarps - hist_warps;
    for (int node = wl; node < NUM_NODES; node += nl) {
        const float* feat = (node < NUM_USERS)
            ? uemb + (size_t)node * EMB
            : iemb + (size_t)(node - NUM_USERS) * EMB;
        float x0 = __ldg(&feat[lane]);
        float x1 = __ldg(&feat[lane + 32]);
        float acc = bias;
#pragma unroll
        for (int k = 0; k < 32; k++) {
            acc += __shfl_sync(0xffffffffu, x0, k) * w[k];
            acc += __shfl_sync(0xffffffffu, x1, k) * w[k + 32];
        }
        g_h1h[(size_t)node * HID + lane] = __float2half_rn(acc);
    }
}

// ---------------------------------------------------------------------------
// Single-pass exclusive scan (decoupled lookback), 98 blocks.
__global__ void scan_kernel() {
    __shared__ int sh[SCAN_BLK];
    __shared__ int s_prefix;
    int tid = threadIdx.x;
    int b = blockIdx.x;
    int i = b * SCAN_BLK + tid;
    int v = (i < NUM_NODES) ? g_counts[i] : 0;
    sh[tid] = v;
    __syncthreads();
#pragma unroll
    for (int off = 1; off < SCAN_BLK; off <<= 1) {
        int t = (tid >= off) ? sh[tid - off] : 0;
        __syncthreads();
        sh[tid] += t;
        __syncthreads();
    }
    int incl = sh[tid];
    int agg = sh[SCAN_BLK - 1];

    if (tid == 0) {
        int st = ((b == 0) ? ST_INCL : ST_AGG) | agg;
        atomicExch(&g_tile_state[b], st);
        if (b == 0) s_prefix = 0;
    }

    if (b > 0 && tid < 32) {
        int running = 0;
        int idx = b - 1;
        while (true) {
            int look = idx - tid;
            int st;
            if (look >= 0) {
                do { st = atomicAdd(&g_tile_state[look], 0); } while (st == 0);
            } else {
                st = ST_INCL;
            }
            int status = st & ~ST_VAL;
            int val    = st & ST_VAL;
            unsigned mask = __ballot_sync(0xffffffffu, status == ST_INCL);
            if (mask) {
                int first = __ffs(mask) - 1;
                int contrib = (tid <= first) ? val : 0;
#pragma unroll
                for (int o = 16; o > 0; o >>= 1)
                    contrib += __shfl_xor_sync(0xffffffffu, contrib, o);
                running += contrib;
                break;
            } else {
                int contrib = val;
#pragma unroll
                for (int o = 16; o > 0; o >>= 1)
                    contrib += __shfl_xor_sync(0xffffffffu, contrib, o);
                running += contrib;
                idx -= 32;
            }
        }
        if (tid == 0) {
            atomicExch(&g_tile_state[b], ST_INCL | (running + agg));
            s_prefix = running;
        }
    }
    __syncthreads();

    int prefix = s_prefix;
    if (i < NUM_NODES) {
        int excl = prefix + incl - v;
        g_row_ptr[i] = excl;
        g_counts[i]  = excl;          // cursor for permute
    }
    if (b == NB - 1 && tid == 0) g_row_ptr[NUM_NODES] = N_EDGES;
}

// ---------------------------------------------------------------------------
// CSR permute: 4 edges/thread
__global__ void permute_kernel(const int* __restrict__ rows,
                               const int* __restrict__ cols,
                               const float* __restrict__ vals) {
    int t = blockIdx.x * blockDim.x + threadIdx.x;
    int e4 = t * 4;
    if (e4 + 3 < N_EDGES) {
        int4   r4 = *(const int4*)(rows + e4);
        int4   c4 = *(const int4*)(cols + e4);
        float4 v4 = *(const float4*)(vals + e4);
        int p0 = atomicAdd(&g_counts[r4.x], 1);
        int p1 = atomicAdd(&g_counts[r4.y], 1);
        int p2 = atomicAdd(&g_counts[r4.z], 1);
        int p3 = atomicAdd(&g_counts[r4.w], 1);
        g_epk[p0] = make_int2(c4.x, __float_as_int(v4.x));
        g_epk[p1] = make_int2(c4.y, __float_as_int(v4.y));
        g_epk[p2] = make_int2(c4.z, __float_as_int(v4.z));
        g_epk[p3] = make_int2(c4.w, __float_as_int(v4.w));
    } else {
        for (int e = e4; e < N_EDGES; e++) {
            int pos = atomicAdd(&g_counts[rows[e]], 1);
            g_epk[pos] = make_int2(cols[e], __float_as_int(vals[e]));
        }
    }
}

// ---------------------------------------------------------------------------
// SpMM layer 1, dual-row quads: quad = (lane>>2) handles rows 2*quad_id and
// 2*quad_id+1 with interleaved edge loops (2 independent gather chains).
// f = lane&3 selects the 16B chunk of the 64B fp16 row.
__global__ void spmm1_kernel() {
    int lane = threadIdx.x & 31;
    int f = lane & 3;
    int q = lane >> 2;
    int warp   = blockIdx.x * (blockDim.x >> 5) + (threadIdx.x >> 5);
    int nquads = gridDim.x * (blockDim.x >> 5) * 8;
    const uint4* tbl = (const uint4*)g_h1h;

    for (int r0 = (warp * 8 + q) * 2; r0 < NUM_NODES; r0 += 2 * nquads) {
        int r1 = r0 + 1;
        bool has1 = (r1 < NUM_NODES);
        int jb0 = __ldg(&g_row_ptr[r0]);
        int mid = __ldg(&g_row_ptr[r0 + 1]);
        int je1 = has1 ? __ldg(&g_row_ptr[r0 + 2]) : mid;
        int n0 = mid - jb0;
        int n1 = je1 - mid;

        float acc0[8], acc1[8];
#pragma unroll
        for (int i = 0; i < 8; i++) { acc0[i] = 0.f; acc1[i] = 0.f; }

        int n = n0 > n1 ? n0 : n1;
#pragma unroll 2
        for (int t = 0; t < n; t++) {
            if (t < n0) {
                int2 cv = __ldg(&g_epk[jb0 + t]);
                float v = __int_as_float(cv.y);
                uint4 hq = __ldg(&tbl[(size_t)cv.x * 4 + f]);
                const __half2* hp = (const __half2*)&hq;
#pragma unroll
                for (int i = 0; i < 4; i++) {
                    float2 hf = __half22float2(hp[i]);
                    acc0[2 * i]     += v * hf.x;
                    acc0[2 * i + 1] += v * hf.y;
                }
            }
            if (t < n1) {
                int2 cv = __ldg(&g_epk[mid + t]);
                float v = __int_as_float(cv.y);
                uint4 hq = __ldg(&tbl[(size_t)cv.x * 4 + f]);
                const __half2* hp = (const __half2*)&hq;
#pragma unroll
                for (int i = 0; i < 4; i++) {
                    float2 hf = __half22float2(hp[i]);
                    acc1[2 * i]     += v * hf.x;
                    acc1[2 * i + 1] += v * hf.y;
                }
            }
        }
        {
            __half2 oh[4];
#pragma unroll
            for (int i = 0; i < 4; i++)
                oh[i] = __floats2half2_rn(fmaxf(acc0[2 * i], 0.f),
                                          fmaxf(acc0[2 * i + 1], 0.f));
            ((uint4*)g_yh)[(size_t)r0 * 4 + f] = *(const uint4*)oh;
        }
        if (has1) {
            __half2 oh[4];
#pragma unroll
            for (int i = 0; i < 4; i++)
                oh[i] = __floats2half2_rn(fmaxf(acc1[2 * i], 0.f),
                                          fmaxf(acc1[2 * i + 1], 0.f));
            ((uint4*)g_yh)[(size_t)r1 * 4 + f] = *(const uint4*)oh;
        }
    }
}

// ---------------------------------------------------------------------------
// SpMM layer 2, dual-row quads; writes agg TRANSPOSED + rowsum.
__global__ void spmm2_kernel() {
    int lane = threadIdx.x & 31;
    int f = lane & 3;
    int q = lane >> 2;
    int warp   = blockIdx.x * (blockDim.x >> 5) + (threadIdx.x >> 5);
    int nquads = gridDim.x * (blockDim.x >> 5) * 8;
    const uint4* tbl = (const uint4*)g_yh;

    for (int r0 = (warp * 8 + q) * 2; r0 < NUM_NODES; r0 += 2 * nquads) {
        int r1 = r0 + 1;
        bool has1 = (r1 < NUM_NODES);
        int jb0 = __ldg(&g_row_ptr[r0]);
        int mid = __ldg(&g_row_ptr[r0 + 1]);
        int je1 = has1 ? __ldg(&g_row_ptr[r0 + 2]) : mid;
        int n0 = mid - jb0;
        int n1 = je1 - mid;

        float acc0[8], acc1[8];
#pragma unroll
        for (int i = 0; i < 8; i++) { acc0[i] = 0.f; acc1[i] = 0.f; }
        float s0 = 0.f, s1 = 0.f;

        int n = n0 > n1 ? n0 : n1;
#pragma unroll 2
        for (int t = 0; t < n; t++) {
            if (t < n0) {
                int2 cv = __ldg(&g_epk[jb0 + t]);
                float v = __int_as_float(cv.y);
                uint4 hq = __ldg(&tbl[(size_t)cv.x * 4 + f]);
                const __half2* hp = (const __half2*)&hq;
#pragma unroll
                for (int i = 0; i < 4; i++) {
                    float2 hf = __half22float2(hp[i]);
                    acc0[2 * i]     += v * hf.x;
                    acc0[2 * i + 1] += v * hf.y;
                }
                s0 += v;
            }
            if (t < n1) {
                int2 cv = __ldg(&g_epk[mid + t]);
                float v = __int_as_float(cv.y);
                uint4 hq = __ldg(&tbl[(size_t)cv.x * 4 + f]);
                const __half2* hp = (const __half2*)&hq;
#pragma unroll
                for (int i = 0; i < 4; i++) {
                    float2 hf = __half22float2(hp[i]);
                    acc1[2 * i]     += v * hf.x;
                    acc1[2 * i + 1] += v * hf.y;
                }
                s1 += v;
            }
        }
#pragma unroll
        for (int i = 0; i < 8; i++) {
            g_aggT[(size_t)(f * 8 + i) * NUM_NODES + r0] = acc0[i];
            if (has1) g_aggT[(size_t)(f * 8 + i) * NUM_NODES + r1] = acc1[i];
        }
        if (f == 0) {
            g_s[r0] = s0;
            if (has1) g_s[r1] = s1;
        }
    }
}

// ---------------------------------------------------------------------------
// lin2out: out[r][o] = relu( sum_k aggT[k][r]*W2[o][k] + s[r]*b2[o] ).
__global__ void lin2out_kernel(const float* __restrict__ W2,
                               const float* __restrict__ b2,
                               float* __restrict__ out_h2) {
    int lane = threadIdx.x & 31;
    float w0[HID], w1[HID];
#pragma unroll
    for (int k = 0; k < HID; k++) {
        w0[k] = __ldg(&W2[lane * HID + k]);
        w1[k] = __ldg(&W2[(lane + 32) * HID + k]);
    }
    float b0 = __ldg(&b2[lane]);
    float b1 = __ldg(&b2[lane + 32]);

    int warp   = blockIdx.x * (blockDim.x >> 5) + (threadIdx.x >> 5);
    int nwarps = gridDim.x * (blockDim.x >> 5);
    const int NGROUPS = NUM_NODES / 8;   // 12500

    for (int grp = warp; grp < NGROUPS; grp += nwarps) {
        int n0 = grp * 8;
        float a0[8], a1[8];
        {
            const float4* sp = (const float4*)(g_s + n0);
            float4 s01 = __ldg(&sp[0]);
            float4 s23 = __ldg(&sp[1]);
            a0[0] = s01.x * b0; a1[0] = s01.x * b1;
            a0[1] = s01.y * b0; a1[1] = s01.y * b1;
            a0[2] = s01.z * b0; a1[2] = s01.z * b1;
            a0[3] = s01.w * b0; a1[3] = s01.w * b1;
            a0[4] = s23.x * b0; a1[4] = s23.x * b1;
            a0[5] = s23.y * b0; a1[5] = s23.y * b1;
            a0[6] = s23.z * b0; a1[6] = s23.z * b1;
            a0[7] = s23.w * b0; a1[7] = s23.w * b1;
        }
#pragma unroll
        for (int k = 0; k < HID; k++) {
            const float4* ap = (const float4*)(g_aggT + (size_t)k * NUM_NODES + n0);
            float4 x03 = __ldg(&ap[0]);
            float4 x47 = __ldg(&ap[1]);
            a0[0] += x03.x * w0[k]; a1[0] += x03.x * w1[k];
            a0[1] += x03.y * w0[k]; a1[1] += x03.y * w1[k];
            a0[2] += x03.z * w0[k]; a1[2] += x03.z * w1[k];
            a0[3] += x03.w * w0[k]; a1[3] += x03.w * w1[k];
            a0[4] += x47.x * w0[k]; a1[4] += x47.x * w1[k];
            a0[5] += x47.y * w0[k]; a1[5] += x47.y * w1[k];
            a0[6] += x47.z * w0[k]; a1[6] += x47.z * w1[k];
            a0[7] += x47.w * w0[k]; a1[7] += x47.w * w1[k];
        }
#pragma unroll
        for (int n = 0; n < 8; n++) {
            out_h2[(size_t)(n0 + n) * EMB + lane]      = fmaxf(a0[n], 0.f);
            out_h2[(size_t)(n0 + n) * EMB + lane + 32] = fmaxf(a1[n], 0.f);
        }
    }
}

// ---------------------------------------------------------------------------
// prediction MLP + state cleanup (restores the zeroed-counts invariant).
__global__ void predict_kernel(const int* __restrict__ uid,
                               const int* __restrict__ iid,
                               const float* __restrict__ h2,
                               const float* __restrict__ p1w,
                               const float* __restrict__ p1b,
                               const float* __restrict__ p2w,
                               const float* __restrict__ p2b,
                               float* __restrict__ scores) {
    int gt = blockIdx.x * blockDim.x + threadIdx.x;
    int nthr = gridDim.x * blockDim.x;
    for (int i = gt; i < NUM_NODES; i += nthr) g_counts[i] = 0;
    if (gt < NB) g_tile_state[gt] = 0;

    int lane = threadIdx.x & 31;
    float w[2 * EMB];
#pragma unroll
    for (int k = 0; k < 2 * EMB; k++) w[k] = __ldg(&p1w[lane * 2 * EMB + k]);
    float bias = __ldg(&p1b[lane]);
    float w2   = __ldg(&p2w[lane]);
    float b2v  = __ldg(&p2b[0]);

    int warp   = blockIdx.x * (blockDim.x >> 5) + (threadIdx.x >> 5);
    int nwarps = gridDim.x * (blockDim.x >> 5);

    for (int s = warp; s < BATCH; s += nwarps) {
        int u  = __ldg(&uid[s]);
        int it = __ldg(&iid[s]);
        const float* bu = h2 + (size_t)u * EMB;
        const float* bi = h2 + (size_t)(NUM_USERS + it) * EMB;
        float x0 = bu[lane], x1 = bu[lane + 32];
        float x2 = bi[lane], x3 = bi[lane + 32];
        float acc = bias;
#pragma unroll
        for (int k = 0; k < 32; k++) {
            acc += __shfl_sync(0xffffffffu, x0, k) * w[k];
            acc += __shfl_sync(0xffffffffu, x1, k) * w[k + 32];
            acc += __shfl_sync(0xffffffffu, x2, k) * w[k + 64];
            acc += __shfl_sync(0xffffffffu, x3, k) * w[k + 96];
        }
        float z = fmaxf(acc, 0.f) * w2;
#pragma unroll
        for (int o = 16; o > 0; o >>= 1)
            z += __shfl_xor_sync(0xffffffffu, z, o);
        if (lane == 0)
            scores[s] = 1.f / (1.f + expf(-(z + b2v)));
    }
}

// ---------------------------------------------------------------------------
extern "C" void kernel_launch(void* const* d_in, const int* in_sizes, int n_in,
                              void* d_out, int out_size) {
    const int*   user_ids = (const int*)d_in[0];
    const int*   item_ids = (const int*)d_in[1];
    const int*   adj_rows = (const int*)d_in[2];
    const int*   adj_cols = (const int*)d_in[3];
    const float* adj_vals = (const float*)d_in[4];
    const float* uemb     = (const float*)d_in[5];
    const float* iemb     = (const float*)d_in[6];
    const float* gc1w     = (const float*)d_in[7];
    const float* gc1b     = (const float*)d_in[8];
    const float* gc2w     = (const float*)d_in[9];
    const float* gc2b     = (const float*)d_in[10];
    const float* p1w      = (const float*)d_in[11];
    const float* p1b      = (const float*)d_in[12];
    const float* p2w      = (const float*)d_in[13];
    const float* p2b      = (const float*)d_in[14];

    float* out    = (float*)d_out;
    float* out_h2 = out + BATCH;   // [NUM_NODES*EMB] = concat(user_emb, item_emb)

    const int TB = 256;
    const int E4 = (N_EDGES / 4 + TB - 1) / TB;

    // 1: fused lin1 (fp16 table) + degree histogram
    lin1_hist_kernel<<<592, TB>>>(uemb, iemb, gc1w, gc1b, adj_rows);
    // 2: single-pass lookback scan -> row_ptr + cursor
    scan_kernel<<<NB, SCAN_BLK>>>();
    // 3: CSR permute
    permute_kernel<<<E4, TB>>>(adj_rows, adj_cols, adj_vals);
    // 4: layer-1 aggregate + ReLU (dual-row quads)
    spmm1_kernel<<<1184, TB>>>();
    // 5: layer-2 aggregate -> transposed agg + rowsum (dual-row quads)
    spmm2_kernel<<<1184, TB>>>();
    // 6: dense lin2 + bias + ReLU -> d_out embeddings
    lin2out_kernel<<<1184, TB>>>(gc2w, gc2b, out_h2);
    // 7: prediction head + state cleanup
    predict_kernel<<<148, TB>>>(user_ids, item_ids, out_h2,
                                p1w, p1b, p2w, p2b, out);
}

// round 13
// speedup vs baseline: 1.0555x; 1.0555x over previous
#include <cuda_runtime.h>
#include <cuda_fp16.h>
#include <math.h>

#define NUM_USERS 60000
#define NUM_ITEMS 40000
#define NUM_NODES 100000
#define EMB 64
#define HID 32
#define N_EDGES 1600000
#define BATCH 16384

#define SCAN_BLK 1024
#define NB ((NUM_NODES + SCAN_BLK - 1) / SCAN_BLK)   // 98

#define ST_AGG  (1 << 30)
#define ST_INCL (2 << 30)
#define ST_VAL  0x3FFFFFFF

// ---------------- device scratch (allocation-free rule) ----------------
__device__ __align__(16) __half g_h1h[NUM_NODES * HID];   // lin1 out, fp16 (64B/row)
__device__ __align__(16) __half g_yh[NUM_NODES * HID];    // relu(agg1), fp16 (64B/row)
__device__ __align__(16) float  g_aggT[HID * NUM_NODES];  // layer-2 agg, TRANSPOSED [k][node]
__device__ float g_s[NUM_NODES];                          // per-row sum of vals
__device__ int   g_counts[NUM_NODES];                     // degree hist / cursor (zeroed by predict tail)
__device__ int   g_row_ptr[NUM_NODES + 1];
__device__ int   g_tile_state[NB];                        // lookback states (zeroed by predict tail)
__device__ __align__(8) int2 g_epk[N_EDGES];              // (col, val-bits), CSR order

// ---------------------------------------------------------------------------
// Fused lin1 + degree histogram (warp-role split). Counts pre-zeroed invariant.
__global__ void lin1_hist_kernel(const float* __restrict__ uemb,
                                 const float* __restrict__ iemb,
                                 const float* __restrict__ W,
                                 const float* __restrict__ b,
                                 const int* __restrict__ rows) {
    int lane = threadIdx.x & 31;
    int wid  = blockIdx.x * (blockDim.x >> 5) + (threadIdx.x >> 5);
    int nwarps = gridDim.x * (blockDim.x >> 5);
    int hist_warps = nwarps >> 2;

    if (wid < hist_warps) {
        int t = wid * 32 + lane;
        int nthr = hist_warps * 32;
        for (int e4 = t * 4; e4 < N_EDGES; e4 += nthr * 4) {
            int4 r4 = *(const int4*)(rows + e4);      // N_EDGES % 4 == 0
            atomicAdd(&g_counts[r4.x], 1);
            atomicAdd(&g_counts[r4.y], 1);
            atomicAdd(&g_counts[r4.z], 1);
            atomicAdd(&g_counts[r4.w], 1);
        }
        return;
    }

    float w[EMB];
#pragma unroll
    for (int k = 0; k < EMB; k++) w[k] = __ldg(&W[lane * EMB + k]);
    float bias = __ldg(&b[lane]);

    int wl = wid - hist_warps;
    int nl = nwarps - hist_warps;
    for (int node = wl; node < NUM_NODES; node += nl) {
        const float* feat = (node < NUM_USERS)
            ? uemb + (size_t)node * EMB
            : iemb + (size_t)(node - NUM_USERS) * EMB;
        float x0 = __ldg(&feat[lane]);
        float x1 = __ldg(&feat[lane + 32]);
        float acc = bias;
#pragma unroll
        for (int k = 0; k < 32; k++) {
            acc += __shfl_sync(0xffffffffu, x0, k) * w[k];
            acc += __shfl_sync(0xffffffffu, x1, k) * w[k + 32];
        }
        g_h1h[(size_t)node * HID + lane] = __float2half_rn(acc);
    }
}

// ---------------------------------------------------------------------------
// Single-pass exclusive scan (decoupled lookback), 98 blocks.
__global__ void scan_kernel() {
    __shared__ int sh[SCAN_BLK];
    __shared__ int s_prefix;
    int tid = threadIdx.x;
    int b = blockIdx.x;
    int i = b * SCAN_BLK + tid;
    int v = (i < NUM_NODES) ? g_counts[i] : 0;
    sh[tid] = v;
    __syncthreads();
#pragma unroll
    for (int off = 1; off < SCAN_BLK; off <<= 1) {
        int t = (tid >= off) ? sh[tid - off] : 0;
        __syncthreads();
        sh[tid] += t;
        __syncthreads();
    }
    int incl = sh[tid];
    int agg = sh[SCAN_BLK - 1];

    if (tid == 0) {
        int st = ((b == 0) ? ST_INCL : ST_AGG) | agg;
        atomicExch(&g_tile_state[b], st);
        if (b == 0) s_prefix = 0;
    }

    if (b > 0 && tid < 32) {
        int running = 0;
        int idx = b - 1;
        while (true) {
            int look = idx - tid;
            int st;
            if (look >= 0) {
                do { st = atomicAdd(&g_tile_state[look], 0); } while (st == 0);
            } else {
                st = ST_INCL;
            }
            int status = st & ~ST_VAL;
            int val    = st & ST_VAL;
            unsigned mask = __ballot_sync(0xffffffffu, status == ST_INCL);
            if (mask) {
                int first = __ffs(mask) - 1;
                int contrib = (tid <= first) ? val : 0;
#pragma unroll
                for (int o = 16; o > 0; o >>= 1)
                    contrib += __shfl_xor_sync(0xffffffffu, contrib, o);
                running += contrib;
                break;
            } else {
                int contrib = val;
#pragma unroll
                for (int o = 16; o > 0; o >>= 1)
                    contrib += __shfl_xor_sync(0xffffffffu, contrib, o);
                running += contrib;
                idx -= 32;
            }
        }
        if (tid == 0) {
            atomicExch(&g_tile_state[b], ST_INCL | (running + agg));
            s_prefix = running;
        }
    }
    __syncthreads();

    int prefix = s_prefix;
    if (i < NUM_NODES) {
        int excl = prefix + incl - v;
        g_row_ptr[i] = excl;
        g_counts[i]  = excl;          // cursor for permute
    }
    if (b == NB - 1 && tid == 0) g_row_ptr[NUM_NODES] = N_EDGES;
}

// ---------------------------------------------------------------------------
// CSR permute: 4 edges/thread
__global__ void permute_kernel(const int* __restrict__ rows,
                               const int* __restrict__ cols,
                               const float* __restrict__ vals) {
    int t = blockIdx.x * blockDim.x + threadIdx.x;
    int e4 = t * 4;
    if (e4 + 3 < N_EDGES) {
        int4   r4 = *(const int4*)(rows + e4);
        int4   c4 = *(const int4*)(cols + e4);
        float4 v4 = *(const float4*)(vals + e4);
        int p0 = atomicAdd(&g_counts[r4.x], 1);
        int p1 = atomicAdd(&g_counts[r4.y], 1);
        int p2 = atomicAdd(&g_counts[r4.z], 1);
        int p3 = atomicAdd(&g_counts[r4.w], 1);
        g_epk[p0] = make_int2(c4.x, __float_as_int(v4.x));
        g_epk[p1] = make_int2(c4.y, __float_as_int(v4.y));
        g_epk[p2] = make_int2(c4.z, __float_as_int(v4.z));
        g_epk[p3] = make_int2(c4.w, __float_as_int(v4.w));
    } else {
        for (int e = e4; e < N_EDGES; e++) {
            int pos = atomicAdd(&g_counts[rows[e]], 1);
            g_epk[pos] = make_int2(cols[e], __float_as_int(vals[e]));
        }
    }
}

// ---------------------------------------------------------------------------
// SpMM layer 1, QUAD-per-row (R10 form): lane=(q,f), q=lane>>2 row subquad,
// f=lane&3 16B chunk of the 64B fp16 row. No cross-lane reduction.
// __launch_bounds__(256,8): cap regs at 32 -> full 2048-thread residency.
__global__ void __launch_bounds__(256, 8) spmm1_kernel() {
    int lane = threadIdx.x & 31;
    int f = lane & 3;
    int q = lane >> 2;
    int warp   = blockIdx.x * (blockDim.x >> 5) + (threadIdx.x >> 5);
    int nquads = gridDim.x * (blockDim.x >> 5) * 8;
    const uint4* tbl = (const uint4*)g_h1h;

    for (int r = warp * 8 + q; r < NUM_NODES; r += nquads) {
        int jb = __ldg(&g_row_ptr[r]);
        int je = __ldg(&g_row_ptr[r + 1]);
        float acc[8];
#pragma unroll
        for (int i = 0; i < 8; i++) acc[i] = 0.f;
#pragma unroll 4
        for (int j = jb; j < je; j++) {
            int2 cv = __ldg(&g_epk[j]);              // uniform within quad
            float v = __int_as_float(cv.y);
            uint4 hq = __ldg(&tbl[(size_t)cv.x * 4 + f]);
            const __half2* hp = (const __half2*)&hq;
#pragma unroll
            for (int i = 0; i < 4; i++) {
                float2 hf = __half22float2(hp[i]);
                acc[2 * i]     += v * hf.x;
                acc[2 * i + 1] += v * hf.y;
            }
        }
        __half2 oh[4];
#pragma unroll
        for (int i = 0; i < 4; i++)
            oh[i] = __floats2half2_rn(fmaxf(acc[2 * i], 0.f),
                                      fmaxf(acc[2 * i + 1], 0.f));
        ((uint4*)g_yh)[(size_t)r * 4 + f] = *(const uint4*)oh;
    }
}

// ---------------------------------------------------------------------------
// SpMM layer 2, QUAD-per-row (R10 form): agg TRANSPOSED + rowsum.
__global__ void __launch_bounds__(256, 8) spmm2_kernel() {
    int lane = threadIdx.x & 31;
    int f = lane & 3;
    int q = lane >> 2;
    int warp   = blockIdx.x * (blockDim.x >> 5) + (threadIdx.x >> 5);
    int nquads = gridDim.x * (blockDim.x >> 5) * 8;
    const uint4* tbl = (const uint4*)g_yh;

    for (int r = warp * 8 + q; r < NUM_NODES; r += nquads) {
        int jb = __ldg(&g_row_ptr[r]);
        int je = __ldg(&g_row_ptr[r + 1]);
        float acc[8];
#pragma unroll
        for (int i = 0; i < 8; i++) acc[i] = 0.f;
        float s = 0.f;
#pragma unroll 4
        for (int j = jb; j < je; j++) {
            int2 cv = __ldg(&g_epk[j]);
            float v = __int_as_float(cv.y);
            uint4 hq = __ldg(&tbl[(size_t)cv.x * 4 + f]);
            const __half2* hp = (const __half2*)&hq;
#pragma unroll
            for (int i = 0; i < 4; i++) {
                float2 hf = __half22float2(hp[i]);
                acc[2 * i]     += v * hf.x;
                acc[2 * i + 1] += v * hf.y;
            }
            s += v;
        }
#pragma unroll
        for (int i = 0; i < 8; i++)
            g_aggT[(size_t)(f * 8 + i) * NUM_NODES + r] = acc[i];
        if (f == 0) g_s[r] = s;
    }
}

// ---------------------------------------------------------------------------
// lin2out: out[r][o] = relu( sum_k aggT[k][r]*W2[o][k] + s[r]*b2[o] ).
__global__ void lin2out_kernel(const float* __restrict__ W2,
                               const float* __restrict__ b2,
                               float* __restrict__ out_h2) {
    int lane = threadIdx.x & 31;
    float w0[HID], w1[HID];
#pragma unroll
    for (int k = 0; k < HID; k++) {
        w0[k] = __ldg(&W2[lane * HID + k]);
        w1[k] = __ldg(&W2[(lane + 32) * HID + k]);
    }
    float b0 = __ldg(&b2[lane]);
    float b1 = __ldg(&b2[lane + 32]);

    int warp   = blockIdx.x * (blockDim.x >> 5) + (threadIdx.x >> 5);
    int nwarps = gridDim.x * (blockDim.x >> 5);
    const int NGROUPS = NUM_NODES / 8;   // 12500

    for (int grp = warp; grp < NGROUPS; grp += nwarps) {
        int n0 = grp * 8;
        float a0[8], a1[8];
        {
            const float4* sp = (const float4*)(g_s + n0);
            float4 s01 = __ldg(&sp[0]);
            float4 s23 = __ldg(&sp[1]);
            a0[0] = s01.x * b0; a1[0] = s01.x * b1;
            a0[1] = s01.y * b0; a1[1] = s01.y * b1;
            a0[2] = s01.z * b0; a1[2] = s01.z * b1;
            a0[3] = s01.w * b0; a1[3] = s01.w * b1;
            a0[4] = s23.x * b0; a1[4] = s23.x * b1;
            a0[5] = s23.y * b0; a1[5] = s23.y * b1;
            a0[6] = s23.z * b0; a1[6] = s23.z * b1;
            a0[7] = s23.w * b0; a1[7] = s23.w * b1;
        }
#pragma unroll
        for (int k = 0; k < HID; k++) {
            const float4* ap = (const float4*)(g_aggT + (size_t)k * NUM_NODES + n0);
            float4 x03 = __ldg(&ap[0]);          // warp-uniform broadcast
            float4 x47 = __ldg(&ap[1]);
            a0[0] += x03.x * w0[k]; a1[0] += x03.x * w1[k];
            a0[1] += x03.y * w0[k]; a1[1] += x03.y * w1[k];
            a0[2] += x03.z * w0[k]; a1[2] += x03.z * w1[k];
            a0[3] += x03.w * w0[k]; a1[3] += x03.w * w1[k];
            a0[4] += x47.x * w0[k]; a1[4] += x47.x * w1[k];
            a0[5] += x47.y * w0[k]; a1[5] += x47.y * w1[k];
            a0[6] += x47.z * w0[k]; a1[6] += x47.z * w1[k];
            a0[7] += x47.w * w0[k]; a1[7] += x47.w * w1[k];
        }
#pragma unroll
        for (int n = 0; n < 8; n++) {
            out_h2[(size_t)(n0 + n) * EMB + lane]      = fmaxf(a0[n], 0.f);
            out_h2[(size_t)(n0 + n) * EMB + lane + 32] = fmaxf(a1[n], 0.f);
        }
    }
}

// ---------------------------------------------------------------------------
// prediction MLP + state cleanup (restores the zeroed-counts invariant).
__global__ void predict_kernel(const int* __restrict__ uid,
                               const int* __restrict__ iid,
                               const float* __restrict__ h2,
                               const float* __restrict__ p1w,
                               const float* __restrict__ p1b,
                               const float* __restrict__ p2w,
                               const float* __restrict__ p2b,
                               float* __restrict__ scores) {
    int gt = blockIdx.x * blockDim.x + threadIdx.x;
    int nthr = gridDim.x * blockDim.x;
    for (int i = gt; i < NUM_NODES; i += nthr) g_counts[i] = 0;
    if (gt < NB) g_tile_state[gt] = 0;

    int lane = threadIdx.x & 31;
    float w[2 * EMB];
#pragma unroll
    for (int k = 0; k < 2 * EMB; k++) w[k] = __ldg(&p1w[lane * 2 * EMB + k]);
    float bias = __ldg(&p1b[lane]);
    float w2   = __ldg(&p2w[lane]);
    float b2v  = __ldg(&p2b[0]);

    int warp   = blockIdx.x * (blockDim.x >> 5) + (threadIdx.x >> 5);
    int nwarps = gridDim.x * (blockDim.x >> 5);

    for (int s = warp; s < BATCH; s += nwarps) {
        int u  = __ldg(&uid[s]);
        int it = __ldg(&iid[s]);
        const float* bu = h2 + (size_t)u * EMB;
        const float* bi = h2 + (size_t)(NUM_USERS + it) * EMB;
        float x0 = bu[lane], x1 = bu[lane + 32];
        float x2 = bi[lane], x3 = bi[lane + 32];
        float acc = bias;
#pragma unroll
        for (int k = 0; k < 32; k++) {
            acc += __shfl_sync(0xffffffffu, x0, k) * w[k];
            acc += __shfl_sync(0xffffffffu, x1, k) * w[k + 32];
            acc += __shfl_sync(0xffffffffu, x2, k) * w[k + 64];
            acc += __shfl_sync(0xffffffffu, x3, k) * w[k + 96];
        }
        float z = fmaxf(acc, 0.f) * w2;
#pragma unroll
        for (int o = 16; o > 0; o >>= 1)
            z += __shfl_xor_sync(0xffffffffu, z, o);
        if (lane == 0)
            scores[s] = 1.f / (1.f + expf(-(z + b2v)));
    }
}

// ---------------------------------------------------------------------------
extern "C" void kernel_launch(void* const* d_in, const int* in_sizes, int n_in,
                              void* d_out, int out_size) {
    const int*   user_ids = (const int*)d_in[0];
    const int*   item_ids = (const int*)d_in[1];
    const int*   adj_rows = (const int*)d_in[2];
    const int*   adj_cols = (const int*)d_in[3];
    const float* adj_vals = (const float*)d_in[4];
    const float* uemb     = (const float*)d_in[5];
    const float* iemb     = (const float*)d_in[6];
    const float* gc1w     = (const float*)d_in[7];
    const float* gc1b     = (const float*)d_in[8];
    const float* gc2w     = (const float*)d_in[9];
    const float* gc2b     = (const float*)d_in[10];
    const float* p1w      = (const float*)d_in[11];
    const float* p1b      = (const float*)d_in[12];
    const float* p2w      = (const float*)d_in[13];
    const float* p2b      = (const float*)d_in[14];

    float* out    = (float*)d_out;
    float* out_h2 = out + BATCH;   // [NUM_NODES*EMB] = concat(user_emb, item_emb)

    const int TB = 256;
    const int E4 = (N_EDGES / 4 + TB - 1) / TB;

    // 1: fused lin1 (fp16 table) + degree histogram
    lin1_hist_kernel<<<592, TB>>>(uemb, iemb, gc1w, gc1b, adj_rows);
    // 2: single-pass lookback scan -> row_ptr + cursor
    scan_kernel<<<NB, SCAN_BLK>>>();
    // 3: CSR permute
    permute_kernel<<<E4, TB>>>(adj_rows, adj_cols, adj_vals);
    // 4: layer-1 aggregate + ReLU (quad-per-row, full occupancy)
    spmm1_kernel<<<1184, TB>>>();
    // 5: layer-2 aggregate -> transposed agg + rowsum (quad-per-row)
    spmm2_kernel<<<1184, TB>>>();
    // 6: dense lin2 + bias + ReLU -> d_out embeddings
    lin2out_kernel<<<1184, TB>>>(gc2w, gc2b, out_h2);
    // 7: prediction head + state cleanup
    predict_kernel<<<148, TB>>>(user_ids, item_ids, out_h2,
                                p1w, p1b, p2w, p2b, out);
}

// round 14
// speedup vs baseline: 1.1689x; 1.1074x over previous
#include <cuda_runtime.h>
#include <cuda_fp16.h>
#include <math.h>

#define NUM_USERS 60000
#define NUM_ITEMS 40000
#define NUM_NODES 100000
#define EMB 64
#define HID 32
#define N_EDGES 1600000
#define BATCH 16384

#define SCAN_BLK 1024
#define NB ((NUM_NODES + SCAN_BLK - 1) / SCAN_BLK)   // 98

#define ST_AGG  (1 << 30)
#define ST_INCL (2 << 30)
#define ST_VAL  0x3FFFFFFF

// ---------------- device scratch (allocation-free rule) ----------------
__device__ __align__(16) __half g_h1h[NUM_NODES * HID];   // lin1 out, fp16 (64B/row)
__device__ __align__(16) __half g_yh[NUM_NODES * HID];    // relu(agg1), fp16 (64B/row)
__device__ __align__(16) float  g_aggT[HID * NUM_NODES];  // layer-2 agg, TRANSPOSED [k][node]
__device__ float g_s[NUM_NODES];                          // per-row sum of vals
__device__ int   g_counts[NUM_NODES];                     // degree hist / cursor (zeroed by predict tail)
__device__ int   g_row_ptr[NUM_NODES + 1];
__device__ int   g_tile_state[NB];                        // lookback states (zeroed by predict tail)
__device__ __align__(8) int2 g_epk[N_EDGES];              // (col, val-bits), CSR order

// ---------------------------------------------------------------------------
// Fused lin1 + degree histogram (warp-role split). Counts pre-zeroed invariant.
__global__ void lin1_hist_kernel(const float* __restrict__ uemb,
                                 const float* __restrict__ iemb,
                                 const float* __restrict__ W,
                                 const float* __restrict__ b,
                                 const int* __restrict__ rows) {
    int lane = threadIdx.x & 31;
    int wid  = blockIdx.x * (blockDim.x >> 5) + (threadIdx.x >> 5);
    int nwarps = gridDim.x * (blockDim.x >> 5);
    int hist_warps = nwarps >> 2;

    if (wid < hist_warps) {
        int t = wid * 32 + lane;
        int nthr = hist_warps * 32;
        for (int e4 = t * 4; e4 < N_EDGES; e4 += nthr * 4) {
            int4 r4 = *(const int4*)(rows + e4);      // N_EDGES % 4 == 0
            atomicAdd(&g_counts[r4.x], 1);
            atomicAdd(&g_counts[r4.y], 1);
            atomicAdd(&g_counts[r4.z], 1);
            atomicAdd(&g_counts[r4.w], 1);
        }
        return;
    }

    float w[EMB];
#pragma unroll
    for (int k = 0; k < EMB; k++) w[k] = __ldg(&W[lane * EMB + k]);
    float bias = __ldg(&b[lane]);

    int wl = wid - hist_warps;
    int nl = nwarps - hist_warps;
    for (int node = wl; node < NUM_NODES; node += nl) {
        const float* feat = (node < NUM_USERS)
            ? uemb + (size_t)node * EMB
            : iemb + (size_t)(node - NUM_USERS) * EMB;
        float x0 = __ldg(&feat[lane]);
        float x1 = __ldg(&feat[lane + 32]);
        float acc = bias;
#pragma unroll
        for (int k = 0; k < 32; k++) {
            acc += __shfl_sync(0xffffffffu, x0, k) * w[k];
            acc += __shfl_sync(0xffffffffu, x1, k) * w[k + 32];
        }
        g_h1h[(size_t)node * HID + lane] = __float2half_rn(acc);
    }
}

// ---------------------------------------------------------------------------
// Single-pass exclusive scan (decoupled lookback), 98 blocks.
__global__ void scan_kernel() {
    __shared__ int sh[SCAN_BLK];
    __shared__ int s_prefix;
    int tid = threadIdx.x;
    int b = blockIdx.x;
    int i = b * SCAN_BLK + tid;
    int v = (i < NUM_NODES) ? g_counts[i] : 0;
    sh[tid] = v;
    __syncthreads();
#pragma unroll
    for (int off = 1; off < SCAN_BLK; off <<= 1) {
        int t = (tid >= off) ? sh[tid - off] : 0;
        __syncthreads();
        sh[tid] += t;
        __syncthreads();
    }
    int incl = sh[tid];
    int agg = sh[SCAN_BLK - 1];

    if (tid == 0) {
        int st = ((b == 0) ? ST_INCL : ST_AGG) | agg;
        atomicExch(&g_tile_state[b], st);
        if (b == 0) s_prefix = 0;
    }

    if (b > 0 && tid < 32) {
        int running = 0;
        int idx = b - 1;
        while (true) {
            int look = idx - tid;
            int st;
            if (look >= 0) {
                do { st = atomicAdd(&g_tile_state[look], 0); } while (st == 0);
            } else {
                st = ST_INCL;
            }
            int status = st & ~ST_VAL;
            int val    = st & ST_VAL;
            unsigned mask = __ballot_sync(0xffffffffu, status == ST_INCL);
            if (mask) {
                int first = __ffs(mask) - 1;
                int contrib = (tid <= first) ? val : 0;
#pragma unroll
                for (int o = 16; o > 0; o >>= 1)
                    contrib += __shfl_xor_sync(0xffffffffu, contrib, o);
                running += contrib;
                break;
            } else {
                int contrib = val;
#pragma unroll
                for (int o = 16; o > 0; o >>= 1)
                    contrib += __shfl_xor_sync(0xffffffffu, contrib, o);
                running += contrib;
                idx -= 32;
            }
        }
        if (tid == 0) {
            atomicExch(&g_tile_state[b], ST_INCL | (running + agg));
            s_prefix = running;
        }
    }
    __syncthreads();

    int prefix = s_prefix;
    if (i < NUM_NODES) {
        int excl = prefix + incl - v;
        g_row_ptr[i] = excl;
        g_counts[i]  = excl;          // cursor for permute
    }
    if (b == NB - 1 && tid == 0) g_row_ptr[NUM_NODES] = N_EDGES;
}

// ---------------------------------------------------------------------------
// CSR permute: 4 edges/thread
__global__ void permute_kernel(const int* __restrict__ rows,
                               const int* __restrict__ cols,
                               const float* __restrict__ vals) {
    int t = blockIdx.x * blockDim.x + threadIdx.x;
    int e4 = t * 4;
    if (e4 + 3 < N_EDGES) {
        int4   r4 = *(const int4*)(rows + e4);
        int4   c4 = *(const int4*)(cols + e4);
        float4 v4 = *(const float4*)(vals + e4);
        int p0 = atomicAdd(&g_counts[r4.x], 1);
        int p1 = atomicAdd(&g_counts[r4.y], 1);
        int p2 = atomicAdd(&g_counts[r4.z], 1);
        int p3 = atomicAdd(&g_counts[r4.w], 1);
        g_epk[p0] = make_int2(c4.x, __float_as_int(v4.x));
        g_epk[p1] = make_int2(c4.y, __float_as_int(v4.y));
        g_epk[p2] = make_int2(c4.z, __float_as_int(v4.z));
        g_epk[p3] = make_int2(c4.w, __float_as_int(v4.w));
    } else {
        for (int e = e4; e < N_EDGES; e++) {
            int pos = atomicAdd(&g_counts[rows[e]], 1);
            g_epk[pos] = make_int2(cols[e], __float_as_int(vals[e]));
        }
    }
}

// ---------------------------------------------------------------------------
// SpMM layer 1, balanced quads: quad q processes EXACTLY rows {2q, 2q+1}
// (contiguous, sequential). Grid sized so nquads*2 covers all rows in one
// pass -> no straggler tail. f=lane&3 is the 16B chunk of the 64B fp16 row.
__global__ void __launch_bounds__(256, 8) spmm1_kernel() {
    int lane = threadIdx.x & 31;
    int f = lane & 3;
    int quad = (blockIdx.x * (blockDim.x >> 5) + (threadIdx.x >> 5)) * 8 + (lane >> 2);
    int r0 = quad * 2;
    if (r0 >= NUM_NODES) return;
    const uint4* tbl = (const uint4*)g_h1h;

    int jb0 = __ldg(&g_row_ptr[r0]);
    int mid = __ldg(&g_row_ptr[r0 + 1]);
    int je1 = __ldg(&g_row_ptr[r0 + 2]);

#pragma unroll
    for (int rr = 0; rr < 2; rr++) {
        int jb = rr ? mid : jb0;
        int je = rr ? je1 : mid;
        float acc[8];
#pragma unroll
        for (int i = 0; i < 8; i++) acc[i] = 0.f;
#pragma unroll 4
        for (int j = jb; j < je; j++) {
            int2 cv = __ldg(&g_epk[j]);              // uniform within quad
            float v = __int_as_float(cv.y);
            uint4 hq = __ldg(&tbl[(size_t)cv.x * 4 + f]);
            const __half2* hp = (const __half2*)&hq;
#pragma unroll
            for (int i = 0; i < 4; i++) {
                float2 hf = __half22float2(hp[i]);
                acc[2 * i]     += v * hf.x;
                acc[2 * i + 1] += v * hf.y;
            }
        }
        __half2 oh[4];
#pragma unroll
        for (int i = 0; i < 4; i++)
            oh[i] = __floats2half2_rn(fmaxf(acc[2 * i], 0.f),
                                      fmaxf(acc[2 * i + 1], 0.f));
        ((uint4*)g_yh)[(size_t)(r0 + rr) * 4 + f] = *(const uint4*)oh;
    }
}

// ---------------------------------------------------------------------------
// SpMM layer 2, balanced quads: agg TRANSPOSED + rowsum.
__global__ void __launch_bounds__(256, 8) spmm2_kernel() {
    int lane = threadIdx.x & 31;
    int f = lane & 3;
    int quad = (blockIdx.x * (blockDim.x >> 5) + (threadIdx.x >> 5)) * 8 + (lane >> 2);
    int r0 = quad * 2;
    if (r0 >= NUM_NODES) return;
    const uint4* tbl = (const uint4*)g_yh;

    int jb0 = __ldg(&g_row_ptr[r0]);
    int mid = __ldg(&g_row_ptr[r0 + 1]);
    int je1 = __ldg(&g_row_ptr[r0 + 2]);

#pragma unroll
    for (int rr = 0; rr < 2; rr++) {
        int jb = rr ? mid : jb0;
        int je = rr ? je1 : mid;
        int r = r0 + rr;
        float acc[8];
#pragma unroll
        for (int i = 0; i < 8; i++) acc[i] = 0.f;
        float s = 0.f;
#pragma unroll 4
        for (int j = jb; j < je; j++) {
            int2 cv = __ldg(&g_epk[j]);
            float v = __int_as_float(cv.y);
            uint4 hq = __ldg(&tbl[(size_t)cv.x * 4 + f]);
            const __half2* hp = (const __half2*)&hq;
#pragma unroll
            for (int i = 0; i < 4; i++) {
                float2 hf = __half22float2(hp[i]);
                acc[2 * i]     += v * hf.x;
                acc[2 * i + 1] += v * hf.y;
            }
            s += v;
        }
#pragma unroll
        for (int i = 0; i < 8; i++)
            g_aggT[(size_t)(f * 8 + i) * NUM_NODES + r] = acc[i];
        if (f == 0) g_s[r] = s;
    }
}

// ---------------------------------------------------------------------------
// lin2out: out[r][o] = relu( sum_k aggT[k][r]*W2[o][k] + s[r]*b2[o] ).
// Balanced: each warp handles 4 consecutive 8-node groups.
__global__ void lin2out_kernel(const float* __restrict__ W2,
                               const float* __restrict__ b2,
                               float* __restrict__ out_h2) {
    int lane = threadIdx.x & 31;
    float w0[HID], w1[HID];
#pragma unroll
    for (int k = 0; k < HID; k++) {
        w0[k] = __ldg(&W2[lane * HID + k]);
        w1[k] = __ldg(&W2[(lane + 32) * HID + k]);
    }
    float b0 = __ldg(&b2[lane]);
    float b1 = __ldg(&b2[lane + 32]);

    int warp = blockIdx.x * (blockDim.x >> 5) + (threadIdx.x >> 5);
    const int NGROUPS = NUM_NODES / 8;   // 12500

#pragma unroll
    for (int gi = 0; gi < 4; gi++) {
        int grp = warp * 4 + gi;
        if (grp >= NGROUPS) return;
        int n0 = grp * 8;
        float a0[8], a1[8];
        {
            const float4* sp = (const float4*)(g_s + n0);
            float4 s01 = __ldg(&sp[0]);
            float4 s23 = __ldg(&sp[1]);
            a0[0] = s01.x * b0; a1[0] = s01.x * b1;
            a0[1] = s01.y * b0; a1[1] = s01.y * b1;
            a0[2] = s01.z * b0; a1[2] = s01.z * b1;
            a0[3] = s01.w * b0; a1[3] = s01.w * b1;
            a0[4] = s23.x * b0; a1[4] = s23.x * b1;
            a0[5] = s23.y * b0; a1[5] = s23.y * b1;
            a0[6] = s23.z * b0; a1[6] = s23.z * b1;
            a0[7] = s23.w * b0; a1[7] = s23.w * b1;
        }
#pragma unroll
        for (int k = 0; k < HID; k++) {
            const float4* ap = (const float4*)(g_aggT + (size_t)k * NUM_NODES + n0);
            float4 x03 = __ldg(&ap[0]);          // warp-uniform broadcast
            float4 x47 = __ldg(&ap[1]);
            a0[0] += x03.x * w0[k]; a1[0] += x03.x * w1[k];
            a0[1] += x03.y * w0[k]; a1[1] += x03.y * w1[k];
            a0[2] += x03.z * w0[k]; a1[2] += x03.z * w1[k];
            a0[3] += x03.w * w0[k]; a1[3] += x03.w * w1[k];
            a0[4] += x47.x * w0[k]; a1[4] += x47.x * w1[k];
            a0[5] += x47.y * w0[k]; a1[5] += x47.y * w1[k];
            a0[6] += x47.z * w0[k]; a1[6] += x47.z * w1[k];
            a0[7] += x47.w * w0[k]; a1[7] += x47.w * w1[k];
        }
#pragma unroll
        for (int n = 0; n < 8; n++) {
            out_h2[(size_t)(n0 + n) * EMB + lane]      = fmaxf(a0[n], 0.f);
            out_h2[(size_t)(n0 + n) * EMB + lane + 32] = fmaxf(a1[n], 0.f);
        }
    }
}

// ---------------------------------------------------------------------------
// prediction MLP + state cleanup (restores the zeroed-counts invariant).
__global__ void predict_kernel(const int* __restrict__ uid,
                               const int* __restrict__ iid,
                               const float* __restrict__ h2,
                               const float* __restrict__ p1w,
                               const float* __restrict__ p1b,
                               const float* __restrict__ p2w,
                               const float* __restrict__ p2b,
                               float* __restrict__ scores) {
    int gt = blockIdx.x * blockDim.x + threadIdx.x;
    int nthr = gridDim.x * blockDim.x;
    for (int i = gt; i < NUM_NODES; i += nthr) g_counts[i] = 0;
    if (gt < NB) g_tile_state[gt] = 0;

    int lane = threadIdx.x & 31;
    float w[2 * EMB];
#pragma unroll
    for (int k = 0; k < 2 * EMB; k++) w[k] = __ldg(&p1w[lane * 2 * EMB + k]);
    float bias = __ldg(&p1b[lane]);
    float w2   = __ldg(&p2w[lane]);
    float b2v  = __ldg(&p2b[0]);

    int warp   = blockIdx.x * (blockDim.x >> 5) + (threadIdx.x >> 5);
    int nwarps = gridDim.x * (blockDim.x >> 5);

    for (int s = warp; s < BATCH; s += nwarps) {
        int u  = __ldg(&uid[s]);
        int it = __ldg(&iid[s]);
        const float* bu = h2 + (size_t)u * EMB;
        const float* bi = h2 + (size_t)(NUM_USERS + it) * EMB;
        float x0 = bu[lane], x1 = bu[lane + 32];
        float x2 = bi[lane], x3 = bi[lane + 32];
        float acc = bias;
#pragma unroll
        for (int k = 0; k < 32; k++) {
            acc += __shfl_sync(0xffffffffu, x0, k) * w[k];
            acc += __shfl_sync(0xffffffffu, x1, k) * w[k + 32];
            acc += __shfl_sync(0xffffffffu, x2, k) * w[k + 64];
            acc += __shfl_sync(0xffffffffu, x3, k) * w[k + 96];
        }
        float z = fmaxf(acc, 0.f) * w2;
#pragma unroll
        for (int o = 16; o > 0; o >>= 1)
            z += __shfl_xor_sync(0xffffffffu, z, o);
        if (lane == 0)
            scores[s] = 1.f / (1.f + expf(-(z + b2v)));
    }
}

// ---------------------------------------------------------------------------
extern "C" void kernel_launch(void* const* d_in, const int* in_sizes, int n_in,
                              void* d_out, int out_size) {
    const int*   user_ids = (const int*)d_in[0];
    const int*   item_ids = (const int*)d_in[1];
    const int*   adj_rows = (const int*)d_in[2];
    const int*   adj_cols = (const int*)d_in[3];
    const float* adj_vals = (const float*)d_in[4];
    const float* uemb     = (const float*)d_in[5];
    const float* iemb     = (const float*)d_in[6];
    const float* gc1w     = (const float*)d_in[7];
    const float* gc1b     = (const float*)d_in[8];
    const float* gc2w     = (const float*)d_in[9];
    const float* gc2b     = (const float*)d_in[10];
    const float* p1w      = (const float*)d_in[11];
    const float* p1b      = (const float*)d_in[12];
    const float* p2w      = (const float*)d_in[13];
    const float* p2b      = (const float*)d_in[14];

    float* out    = (float*)d_out;
    float* out_h2 = out + BATCH;   // [NUM_NODES*EMB] = concat(user_emb, item_emb)

    const int TB = 256;
    const int E4 = (N_EDGES / 4 + TB - 1) / TB;
    // quads needed = NUM_NODES/2 = 50000; quads/block = 8 warps * 8 = 64
    const int SPMM_BLOCKS = (NUM_NODES / 2 + 63) / 64;        // 782
    const int L2O_BLOCKS  = ((NUM_NODES / 8) + 4 * 8 - 1) / (4 * 8);  // 391

    // 1: fused lin1 (fp16 table) + degree histogram
    lin1_hist_kernel<<<592, TB>>>(uemb, iemb, gc1w, gc1b, adj_rows);
    // 2: single-pass lookback scan -> row_ptr + cursor
    scan_kernel<<<NB, SCAN_BLK>>>();
    // 3: CSR permute
    permute_kernel<<<E4, TB>>>(adj_rows, adj_cols, adj_vals);
    // 4: layer-1 aggregate + ReLU (balanced quads: 2 rows each, one pass)
    spmm1_kernel<<<SPMM_BLOCKS, TB>>>();
    // 5: layer-2 aggregate -> transposed agg + rowsum (balanced quads)
    spmm2_kernel<<<SPMM_BLOCKS, TB>>>();
    // 6: dense lin2 + bias + ReLU -> d_out embeddings (balanced, 4 grp/warp)
    lin2out_kernel<<<L2O_BLOCKS, TB>>>(gc2w, gc2b, out_h2);
    // 7: prediction head + state cleanup
    predict_kernel<<<148, TB>>>(user_ids, item_ids, out_h2,
                                p1w, p1b, p2w, p2b, out);
}

// round 15
// speedup vs baseline: 1.5469x; 1.3233x over previous
#include <cuda_runtime.h>
#include <cuda_fp16.h>
#include <math.h>

#define NUM_USERS 60000
#define NUM_ITEMS 40000
#define NUM_NODES 100000
#define EMB 64
#define HID 32
#define N_EDGES 1600000
#define BATCH 16384

#define SCAN_BLK 1024
#define NB ((NUM_NODES + SCAN_BLK - 1) / SCAN_BLK)   // 98

#define ST_AGG  (1 << 30)
#define ST_INCL (2 << 30)
#define ST_VAL  0x3FFFFFFF

#define HIST_BLOCKS 148

// ---------------- device scratch (allocation-free rule) ----------------
__device__ __align__(16) __half g_h1h[NUM_NODES * HID];   // lin1 out, fp16 (64B/row)
__device__ __align__(16) __half g_yh[NUM_NODES * HID];    // relu(agg1), fp16 (64B/row)
__device__ __align__(16) float  g_agg[NUM_NODES * HID];   // layer-2 agg, row-major [node][k]
__device__ float g_s[NUM_NODES];                          // per-row sum of vals
__device__ int   g_counts[NUM_NODES];                     // degree hist / cursor (zeroed by predict tail)
__device__ int   g_row_ptr[NUM_NODES + 1];
__device__ int   g_tile_state[NB];                        // lookback states (zeroed by predict tail)
__device__ __align__(8) int2 g_epk[N_EDGES];              // (col, val-bits), CSR order

// ---------------------------------------------------------------------------
// Fused lin1 + degree histogram. Blocks [0,HIST_BLOCKS) do the histogram;
// the rest do lin1 with TRANSPOSED smem-staged weights (conflict-free reads).
// g_counts arrives zeroed (restored by predict's tail).
__global__ void lin1_hist_kernel(const float* __restrict__ uemb,
                                 const float* __restrict__ iemb,
                                 const float* __restrict__ W,
                                 const float* __restrict__ b,
                                 const int* __restrict__ rows) {
    int lane = threadIdx.x & 31;

    if (blockIdx.x < HIST_BLOCKS) {
        int t = blockIdx.x * blockDim.x + threadIdx.x;
        int nthr = HIST_BLOCKS * blockDim.x;
        for (int e4 = t * 4; e4 < N_EDGES; e4 += nthr * 4) {
            int4 r4 = *(const int4*)(rows + e4);      // N_EDGES % 4 == 0
            atomicAdd(&g_counts[r4.x], 1);
            atomicAdd(&g_counts[r4.y], 1);
            atomicAdd(&g_counts[r4.z], 1);
            atomicAdd(&g_counts[r4.w], 1);
        }
        return;
    }

    // ---- lin1 blocks ----
    __shared__ float sW[EMB][HID + 1];   // sW[k][j] = W1[j][k]
    int tid = threadIdx.x;
    for (int i = tid; i < HID * EMB; i += blockDim.x) {
        int j = i >> 6, k = i & 63;      // W row-major [j][k], coalesced read
        sW[k][j] = W[i];
    }
    __syncthreads();

    float w[EMB];
#pragma unroll
    for (int k = 0; k < EMB; k++) w[k] = sW[k][lane];   // conflict-free
    float bias = __ldg(&b[lane]);

    int wl = (blockIdx.x - HIST_BLOCKS) * (blockDim.x >> 5) + (tid >> 5);
    int nl = (gridDim.x - HIST_BLOCKS) * (blockDim.x >> 5);

    for (int node = wl; node < NUM_NODES; node += nl) {
        const float* feat = (node < NUM_USERS)
            ? uemb + (size_t)node * EMB
            : iemb + (size_t)(node - NUM_USERS) * EMB;
        float x0 = __ldg(&feat[lane]);
        float x1 = __ldg(&feat[lane + 32]);
        float acc = bias;
#pragma unroll
        for (int k = 0; k < 32; k++) {
            acc += __shfl_sync(0xffffffffu, x0, k) * w[k];
            acc += __shfl_sync(0xffffffffu, x1, k) * w[k + 32];
        }
        g_h1h[(size_t)node * HID + lane] = __float2half_rn(acc);
    }
}

// ---------------------------------------------------------------------------
// Single-pass exclusive scan (decoupled lookback), 98 blocks.
__global__ void scan_kernel() {
    __shared__ int sh[SCAN_BLK];
    __shared__ int s_prefix;
    int tid = threadIdx.x;
    int b = blockIdx.x;
    int i = b * SCAN_BLK + tid;
    int v = (i < NUM_NODES) ? g_counts[i] : 0;
    sh[tid] = v;
    __syncthreads();
#pragma unroll
    for (int off = 1; off < SCAN_BLK; off <<= 1) {
        int t = (tid >= off) ? sh[tid - off] : 0;
        __syncthreads();
        sh[tid] += t;
        __syncthreads();
    }
    int incl = sh[tid];
    int agg = sh[SCAN_BLK - 1];

    if (tid == 0) {
        int st = ((b == 0) ? ST_INCL : ST_AGG) | agg;
        atomicExch(&g_tile_state[b], st);
        if (b == 0) s_prefix = 0;
    }

    if (b > 0 && tid < 32) {
        int running = 0;
        int idx = b - 1;
        while (true) {
            int look = idx - tid;
            int st;
            if (look >= 0) {
                do { st = atomicAdd(&g_tile_state[look], 0); } while (st == 0);
            } else {
                st = ST_INCL;
            }
            int status = st & ~ST_VAL;
            int val    = st & ST_VAL;
            unsigned mask = __ballot_sync(0xffffffffu, status == ST_INCL);
            if (mask) {
                int first = __ffs(mask) - 1;
                int contrib = (tid <= first) ? val : 0;
#pragma unroll
                for (int o = 16; o > 0; o >>= 1)
                    contrib += __shfl_xor_sync(0xffffffffu, contrib, o);
                running += contrib;
                break;
            } else {
                int contrib = val;
#pragma unroll
                for (int o = 16; o > 0; o >>= 1)
                    contrib += __shfl_xor_sync(0xffffffffu, contrib, o);
                running += contrib;
                idx -= 32;
            }
        }
        if (tid == 0) {
            atomicExch(&g_tile_state[b], ST_INCL | (running + agg));
            s_prefix = running;
        }
    }
    __syncthreads();

    int prefix = s_prefix;
    if (i < NUM_NODES) {
        int excl = prefix + incl - v;
        g_row_ptr[i] = excl;
        g_counts[i]  = excl;          // cursor for permute
    }
    if (b == NB - 1 && tid == 0) g_row_ptr[NUM_NODES] = N_EDGES;
}

// ---------------------------------------------------------------------------
// CSR permute: 4 edges/thread
__global__ void permute_kernel(const int* __restrict__ rows,
                               const int* __restrict__ cols,
                               const float* __restrict__ vals) {
    int t = blockIdx.x * blockDim.x + threadIdx.x;
    int e4 = t * 4;
    if (e4 + 3 < N_EDGES) {
        int4   r4 = *(const int4*)(rows + e4);
        int4   c4 = *(const int4*)(cols + e4);
        float4 v4 = *(const float4*)(vals + e4);
        int p0 = atomicAdd(&g_counts[r4.x], 1);
        int p1 = atomicAdd(&g_counts[r4.y], 1);
        int p2 = atomicAdd(&g_counts[r4.z], 1);
        int p3 = atomicAdd(&g_counts[r4.w], 1);
        g_epk[p0] = make_int2(c4.x, __float_as_int(v4.x));
        g_epk[p1] = make_int2(c4.y, __float_as_int(v4.y));
        g_epk[p2] = make_int2(c4.z, __float_as_int(v4.z));
        g_epk[p3] = make_int2(c4.w, __float_as_int(v4.w));
    } else {
        for (int e = e4; e < N_EDGES; e++) {
            int pos = atomicAdd(&g_counts[rows[e]], 1);
            g_epk[pos] = make_int2(cols[e], __float_as_int(vals[e]));
        }
    }
}

// ---------------------------------------------------------------------------
// SpMM layer 1, balanced quads: quad q processes EXACTLY rows {2q, 2q+1}.
__global__ void __launch_bounds__(256, 8) spmm1_kernel() {
    int lane = threadIdx.x & 31;
    int f = lane & 3;
    int quad = (blockIdx.x * (blockDim.x >> 5) + (threadIdx.x >> 5)) * 8 + (lane >> 2);
    int r0 = quad * 2;
    if (r0 >= NUM_NODES) return;
    const uint4* tbl = (const uint4*)g_h1h;

    int jb0 = __ldg(&g_row_ptr[r0]);
    int mid = __ldg(&g_row_ptr[r0 + 1]);
    int je1 = __ldg(&g_row_ptr[r0 + 2]);

#pragma unroll
    for (int rr = 0; rr < 2; rr++) {
        int jb = rr ? mid : jb0;
        int je = rr ? je1 : mid;
        float acc[8];
#pragma unroll
        for (int i = 0; i < 8; i++) acc[i] = 0.f;
#pragma unroll 4
        for (int j = jb; j < je; j++) {
            int2 cv = __ldg(&g_epk[j]);              // uniform within quad
            float v = __int_as_float(cv.y);
            uint4 hq = __ldg(&tbl[(size_t)cv.x * 4 + f]);
            const __half2* hp = (const __half2*)&hq;
#pragma unroll
            for (int i = 0; i < 4; i++) {
                float2 hf = __half22float2(hp[i]);
                acc[2 * i]     += v * hf.x;
                acc[2 * i + 1] += v * hf.y;
            }
        }
        __half2 oh[4];
#pragma unroll
        for (int i = 0; i < 4; i++)
            oh[i] = __floats2half2_rn(fmaxf(acc[2 * i], 0.f),
                                      fmaxf(acc[2 * i + 1], 0.f));
        ((uint4*)g_yh)[(size_t)(r0 + rr) * 4 + f] = *(const uint4*)oh;
    }
}

// ---------------------------------------------------------------------------
// SpMM layer 2, balanced quads: agg ROW-MAJOR (coalesced 128B/row) + rowsum.
__global__ void __launch_bounds__(256, 8) spmm2_kernel() {
    int lane = threadIdx.x & 31;
    int f = lane & 3;
    int quad = (blockIdx.x * (blockDim.x >> 5) + (threadIdx.x >> 5)) * 8 + (lane >> 2);
    int r0 = quad * 2;
    if (r0 >= NUM_NODES) return;
    const uint4* tbl = (const uint4*)g_yh;

    int jb0 = __ldg(&g_row_ptr[r0]);
    int mid = __ldg(&g_row_ptr[r0 + 1]);
    int je1 = __ldg(&g_row_ptr[r0 + 2]);

#pragma unroll
    for (int rr = 0; rr < 2; rr++) {
        int jb = rr ? mid : jb0;
        int je = rr ? je1 : mid;
        int r = r0 + rr;
        float acc[8];
#pragma unroll
        for (int i = 0; i < 8; i++) acc[i] = 0.f;
        float s = 0.f;
#pragma unroll 4
        for (int j = jb; j < je; j++) {
            int2 cv = __ldg(&g_epk[j]);
            float v = __int_as_float(cv.y);
            uint4 hq = __ldg(&tbl[(size_t)cv.x * 4 + f]);
            const __half2* hp = (const __half2*)&hq;
#pragma unroll
            for (int i = 0; i < 4; i++) {
                float2 hf = __half22float2(hp[i]);
                acc[2 * i]     += v * hf.x;
                acc[2 * i + 1] += v * hf.y;
            }
            s += v;
        }
        // coalesced: lane f writes float4 slots 2f, 2f+1 of the 128B row
        float4* ap = (float4*)(g_agg + (size_t)r * HID);
        ap[2 * f]     = make_float4(acc[0], acc[1], acc[2], acc[3]);
        ap[2 * f + 1] = make_float4(acc[4], acc[5], acc[6], acc[7]);
        if (f == 0) g_s[r] = s;
    }
}

// ---------------------------------------------------------------------------
// lin2out: out[n][o] = relu( sum_k agg[n][k]*W2[o][k] + s[n]*b2[o] ).
// Warp handles 32 consecutive nodes; weights smem-transposed -> registers.
__global__ void lin2out_kernel(const float* __restrict__ W2,
                               const float* __restrict__ b2,
                               float* __restrict__ out_h2) {
    __shared__ float sW2[HID][EMB + 1];   // sW2[k][o] = W2[o][k]
    int tid = threadIdx.x;
    for (int i = tid; i < EMB * HID; i += blockDim.x) {
        int o = i >> 5, k = i & 31;       // W2 row-major [o][k], coalesced read
        sW2[k][o] = W2[i];
    }
    __syncthreads();

    int lane = tid & 31;
    float w0[HID], w1[HID];
#pragma unroll
    for (int k = 0; k < HID; k++) {
        w0[k] = sW2[k][lane];             // conflict-free
        w1[k] = sW2[k][lane + 32];
    }
    float b0 = __ldg(&b2[lane]);
    float b1 = __ldg(&b2[lane + 32]);

    int warp = blockIdx.x * (blockDim.x >> 5) + (tid >> 5);
    int n0 = warp * 32;

    for (int n = n0; n < n0 + 32 && n < NUM_NODES; n++) {
        const float4* ap = (const float4*)(g_agg + (size_t)n * HID);
        float s = __ldg(&g_s[n]);
        float a0 = s * b0, a1 = s * b1;
#pragma unroll
        for (int c = 0; c < 8; c++) {
            float4 x = __ldg(&ap[c]);     // warp-uniform broadcast
            int k = c * 4;
            a0 += x.x * w0[k] + x.y * w0[k + 1] + x.z * w0[k + 2] + x.w * w0[k + 3];
            a1 += x.x * w1[k] + x.y * w1[k + 1] + x.z * w1[k + 2] + x.w * w1[k + 3];
        }
        out_h2[(size_t)n * EMB + lane]      = fmaxf(a0, 0.f);
        out_h2[(size_t)n * EMB + lane + 32] = fmaxf(a1, 0.f);
    }
}

// ---------------------------------------------------------------------------
// prediction MLP (smem-transposed weights) + state cleanup.
__global__ void predict_kernel(const int* __restrict__ uid,
                               const int* __restrict__ iid,
                               const float* __restrict__ h2,
                               const float* __restrict__ p1w,
                               const float* __restrict__ p1b,
                               const float* __restrict__ p2w,
                               const float* __restrict__ p2b,
                               float* __restrict__ scores) {
    // cleanup: restore zeroed-counts invariant for the next execution
    int gt = blockIdx.x * blockDim.x + threadIdx.x;
    int nthr = gridDim.x * blockDim.x;
    for (int i = gt; i < NUM_NODES; i += nthr) g_counts[i] = 0;
    if (gt < NB) g_tile_state[gt] = 0;

    __shared__ float sP[2 * EMB][HID + 1];   // sP[k][j] = p1w[j][k]; 16.9KB
    int tid = threadIdx.x;
    for (int i = tid; i < HID * 2 * EMB; i += blockDim.x) {
        int j = i >> 7, k = i & 127;         // p1w row-major [j][k], coalesced
        sP[k][j] = p1w[i];
    }
    __syncthreads();

    int lane = tid & 31;
    float w[2 * EMB];
#pragma unroll
    for (int k = 0; k < 2 * EMB; k++) w[k] = sP[k][lane];   // conflict-free
    float bias = __ldg(&p1b[lane]);
    float w2   = __ldg(&p2w[lane]);
    float b2v  = __ldg(&p2b[0]);

    int warp   = blockIdx.x * (blockDim.x >> 5) + (tid >> 5);
    int nwarps = gridDim.x * (blockDim.x >> 5);

    for (int s = warp; s < BATCH; s += nwarps) {
        int u  = __ldg(&uid[s]);
        int it = __ldg(&iid[s]);
        const float* bu = h2 + (size_t)u * EMB;
        const float* bi = h2 + (size_t)(NUM_USERS + it) * EMB;
        float x0 = bu[lane], x1 = bu[lane + 32];
        float x2 = bi[lane], x3 = bi[lane + 32];
        float acc = bias;
#pragma unroll
        for (int k = 0; k < 32; k++) {
            acc += __shfl_sync(0xffffffffu, x0, k) * w[k];
            acc += __shfl_sync(0xffffffffu, x1, k) * w[k + 32];
            acc += __shfl_sync(0xffffffffu, x2, k) * w[k + 64];
            acc += __shfl_sync(0xffffffffu, x3, k) * w[k + 96];
        }
        float z = fmaxf(acc, 0.f) * w2;
#pragma unroll
        for (int o = 16; o > 0; o >>= 1)
            z += __shfl_xor_sync(0xffffffffu, z, o);
        if (lane == 0)
            scores[s] = 1.f / (1.f + expf(-(z + b2v)));
    }
}

// ---------------------------------------------------------------------------
extern "C" void kernel_launch(void* const* d_in, const int* in_sizes, int n_in,
                              void* d_out, int out_size) {
    const int*   user_ids = (const int*)d_in[0];
    const int*   item_ids = (const int*)d_in[1];
    const int*   adj_rows = (const int*)d_in[2];
    const int*   adj_cols = (const int*)d_in[3];
    const float* adj_vals = (const float*)d_in[4];
    const float* uemb     = (const float*)d_in[5];
    const float* iemb     = (const float*)d_in[6];
    const float* gc1w     = (const float*)d_in[7];
    const float* gc1b     = (const float*)d_in[8];
    const float* gc2w     = (const float*)d_in[9];
    const float* gc2b     = (const float*)d_in[10];
    const float* p1w      = (const float*)d_in[11];
    const float* p1b      = (const float*)d_in[12];
    const float* p2w      = (const float*)d_in[13];
    const float* p2b      = (const float*)d_in[14];

    float* out    = (float*)d_out;
    float* out_h2 = out + BATCH;   // [NUM_NODES*EMB] = concat(user_emb, item_emb)

    const int TB = 256;
    const int E4 = (N_EDGES / 4 + TB - 1) / TB;
    const int SPMM_BLOCKS = (NUM_NODES / 2 + 63) / 64;            // 782
    const int L2O_BLOCKS  = (NUM_NODES + 32 * 8 - 1) / (32 * 8);  // 391

    // 1: fused lin1 (fp16 table, smem-transposed W1) + degree histogram
    lin1_hist_kernel<<<592, TB>>>(uemb, iemb, gc1w, gc1b, adj_rows);
    // 2: single-pass lookback scan -> row_ptr + cursor
    scan_kernel<<<NB, SCAN_BLK>>>();
    // 3: CSR permute
    permute_kernel<<<E4, TB>>>(adj_rows, adj_cols, adj_vals);
    // 4: layer-1 aggregate + ReLU (balanced quads)
    spmm1_kernel<<<SPMM_BLOCKS, TB>>>();
    // 5: layer-2 aggregate -> row-major agg + rowsum (balanced quads)
    spmm2_kernel<<<SPMM_BLOCKS, TB>>>();
    // 6: dense lin2 + bias + ReLU -> d_out embeddings
    lin2out_kernel<<<L2O_BLOCKS, TB>>>(gc2w, gc2b, out_h2);
    // 7: prediction head (smem-transposed p1w) + state cleanup
    predict_kernel<<<148, TB>>>(user_ids, item_ids, out_h2,
                                p1w, p1b, p2w, p2b, out);
}